// round 2
// baseline (speedup 1.0000x reference)
#include <cuda_runtime.h>

#define NB 128
#define THREADS 1024
#define NITER 60

typedef unsigned long long ull;

__device__ __forceinline__ ull pk2(float lo, float hi) {
    ull r; asm("mov.b64 %0, {%1, %2};" : "=l"(r) : "f"(lo), "f"(hi)); return r;
}
__device__ __forceinline__ void upk2(ull v, float& lo, float& hi) {
    asm("mov.b64 {%0, %1}, %2;" : "=f"(lo), "=f"(hi) : "l"(v));
}
__device__ __forceinline__ ull padd2(ull a, ull b) {
    ull r; asm("add.rn.f32x2 %0, %1, %2;" : "=l"(r) : "l"(a), "l"(b)); return r;
}
__device__ __forceinline__ ull psub2(ull a, ull b) {
    ull r; asm("sub.rn.f32x2 %0, %1, %2;" : "=l"(r) : "l"(a), "l"(b)); return r;
}

__global__ void __launch_bounds__(THREADS, 1)
gfusedmax_kernel(const float* __restrict__ x,
                 const float* __restrict__ A,
                 float* __restrict__ out)
{
    const int b     = blockIdx.x;
    const int tid   = threadIdx.x;
    const int lane  = tid & 31;
    const int warp  = tid >> 5;
    const int rbase = warp * 4;          // 4 rows per warp, 32 warps -> 128 rows

    // column pairing: pair cp covers cols (lane + 64*cp, lane + 64*cp + 32)
    __shared__ float2 colpartB[32][2][32];        // 16 KB per-warp column partials
    __shared__ float2 sy2[2][32];                 // step*y, packed per column pair
    __shared__ __align__(16) float sy_row[NB];    // step*y, row-contiguous
    __shared__ float rs_s[NB];                    // row sums (reused as ys after loop)
    __shared__ float sorted_s[NB];
    __shared__ float csum[2][NB];
    __shared__ float wsum[4], wcnt[4];

    const float step = 1.0f / 256.0f;

    // ---- init: clip bounds in registers, z = 0 ----
    float wxr[4][2], wyr[4][2];
    ull z2[4][2];
    const float* Ab = A + (size_t)b * NB * NB;
    #pragma unroll
    for (int r = 0; r < 4; ++r) {
        #pragma unroll
        for (int cp = 0; cp < 2; ++cp) {
            wxr[r][cp] = Ab[(rbase + r) * NB + lane + 64 * cp];       // col c0
            wyr[r][cp] = Ab[(rbase + r) * NB + lane + 64 * cp + 32];  // col c1
            z2[r][cp]  = 0ULL;
        }
    }

    // reducer identity (threads 0..63 own 2 columns each, keep x in regs)
    int cpR = tid >> 5, lR = tid & 31;
    int c0 = lR + 64 * cpR, c1 = c0 + 32;
    float xr0 = 0.0f, xr1 = 0.0f;
    if (tid < 64) {
        xr0 = x[(size_t)b * NB + c0];
        xr1 = x[(size_t)b * NB + c1];
        float s0 = step * xr0, s1 = step * xr1;
        sy2[cpR][lR] = make_float2(s0, s1);
        sy_row[c0] = s0; sy_row[c1] = s1;
    }
    __syncthreads();

    // ---- 60 projected-gradient iterations ----
    #pragma unroll 1
    for (int it = 0; it < NITER; ++it) {
        float2 cf0 = sy2[0][lane];                 // LDS.64, conflict-free
        float2 cf1 = sy2[1][lane];
        ull c2_0 = pk2(cf0.x, cf0.y);
        ull c2_1 = pk2(cf1.x, cf1.y);
        float4 s4 = *reinterpret_cast<const float4*>(&sy_row[rbase]); // LDS.128 bcast
        float syr[4] = {s4.x, s4.y, s4.z, s4.w};

        ull   colacc0 = 0ULL, colacc1 = 0ULL;
        float rowacc[4] = {0.f, 0.f, 0.f, 0.f};

        #pragma unroll
        for (int r = 0; r < 4; ++r) {
            ull s2 = pk2(syr[r], syr[r]);
            // cp = 0
            {
                ull v2 = padd2(z2[r][0], psub2(s2, c2_0));
                float vx, vy; upk2(v2, vx, vy);
                float wa = wxr[r][0], wb = wyr[r][0];
                vx = fminf(fmaxf(vx, -wa), wa);
                vy = fminf(fmaxf(vy, -wb), wb);
                ull zz = pk2(vx, vy);
                z2[r][0] = zz;
                colacc0 = padd2(colacc0, zz);
                rowacc[r] += vx; rowacc[r] += vy;
            }
            // cp = 1
            {
                ull v2 = padd2(z2[r][1], psub2(s2, c2_1));
                float vx, vy; upk2(v2, vx, vy);
                float wa = wxr[r][1], wb = wyr[r][1];
                vx = fminf(fmaxf(vx, -wa), wa);
                vy = fminf(fmaxf(vy, -wb), wb);
                ull zz = pk2(vx, vy);
                z2[r][1] = zz;
                colacc1 = padd2(colacc1, zz);
                rowacc[r] += vx; rowacc[r] += vy;
            }
        }

        // column partials (packed stores)
        {
            float ax, ay;
            upk2(colacc0, ax, ay); colpartB[warp][0][lane] = make_float2(ax, ay);
            upk2(colacc1, ax, ay); colpartB[warp][1][lane] = make_float2(ax, ay);
        }

        // row sums: xor-16 stage, then split 4 values across half-warps (2 chains)
        #pragma unroll
        for (int r = 0; r < 4; ++r)
            rowacc[r] += __shfl_xor_sync(0xffffffffu, rowacc[r], 16);
        bool hi = (lane & 16) != 0;
        float u = hi ? rowacc[1] : rowacc[0];
        float v = hi ? rowacc[3] : rowacc[2];
        #pragma unroll
        for (int s = 8; s > 0; s >>= 1) {
            u += __shfl_xor_sync(0xffffffffu, u, s);
            v += __shfl_xor_sync(0xffffffffu, v, s);
        }
        if (lane == 0)       { rs_s[rbase + 0] = u; rs_s[rbase + 2] = v; }
        else if (lane == 16) { rs_s[rbase + 1] = u; rs_s[rbase + 3] = v; }

        __syncthreads();

        // y-update: 64 threads, 2 columns each, packed 4-way ILP reduction
        if (tid < 64) {
            const ull* cb = reinterpret_cast<const ull*>(&colpartB[0][0][0]);
            int idx = cpR * 32 + lR;
            ull q0 = 0ULL, q1 = 0ULL, q2 = 0ULL, q3 = 0ULL;
            #pragma unroll
            for (int w8 = 0; w8 < 32; w8 += 4) {
                q0 = padd2(q0, cb[(w8 + 0) * 64 + idx]);
                q1 = padd2(q1, cb[(w8 + 1) * 64 + idx]);
                q2 = padd2(q2, cb[(w8 + 2) * 64 + idx]);
                q3 = padd2(q3, cb[(w8 + 3) * 64 + idx]);
            }
            ull q = padd2(padd2(q0, q1), padd2(q2, q3));
            float cs0, cs1; upk2(q, cs0, cs1);
            float y0 = xr0 - rs_s[c0] + cs0;
            float y1 = xr1 - rs_s[c1] + cs1;
            float t0 = step * y0, t1 = step * y1;
            sy2[cpR][lR] = make_float2(t0, t1);
            sy_row[c0] = t0; sy_row[c1] = t1;
        }
        __syncthreads();
    }

    // ---- final y (exact: /256 then *256 is exponent-only) ----
    float yv = 0.0f;
    if (tid < NB) {
        yv = sy_row[tid] * 256.0f;
        rs_s[tid] = yv;                        // reuse rs_s as ys
    }
    __syncthreads();

    // ---- sparsemax: rank sort (branch-free, deterministic) ----
    if (tid < NB) {
        int rank = 0;
        #pragma unroll
        for (int j = 0; j < NB; ++j) {
            float uj = rs_s[j];
            rank += (uj > yv) || (uj == yv && j < tid);
        }
        sorted_s[rank] = yv;                   // descending
    }
    __syncthreads();

    // inclusive scan (Hillis-Steele, ping-pong)
    if (tid < NB) csum[0][tid] = sorted_s[tid];
    __syncthreads();
    int src = 0;
    for (int off = 1; off < NB; off <<= 1) {
        if (tid < NB) {
            float vv = csum[src][tid];
            if (tid >= off) vv += csum[src][tid - off];
            csum[1 - src][tid] = vv;
        }
        __syncthreads();
        src = 1 - src;
    }

    // mask + deterministic (sum, count) reduction
    if (tid < NB) {
        float s  = sorted_s[tid];
        float cu = csum[src][tid];
        float k  = (float)(tid + 1);
        bool  m  = (1.0f + k * s > cu);
        float sv = m ? s : 0.0f;
        float sc = m ? 1.0f : 0.0f;
        #pragma unroll
        for (int sft = 16; sft > 0; sft >>= 1) {
            sv += __shfl_xor_sync(0xffffffffu, sv, sft);
            sc += __shfl_xor_sync(0xffffffffu, sc, sft);
        }
        if (lane == 0) { wsum[warp] = sv; wcnt[warp] = sc; }
    }
    __syncthreads();

    if (tid < NB) {
        float ssum = ((wsum[0] + wsum[1]) + (wsum[2] + wsum[3]));
        float scnt = ((wcnt[0] + wcnt[1]) + (wcnt[2] + wcnt[3]));
        float tau  = (ssum - 1.0f) / scnt;
        out[(size_t)b * NB + tid] = fmaxf(yv - tau, 0.0f);
    }
}

extern "C" void kernel_launch(void* const* d_in, const int* in_sizes, int n_in,
                              void* d_out, int out_size)
{
    const float* x = (const float*)d_in[0];   // [B, 128]
    const float* A = (const float*)d_in[1];   // [B, 128, 128]
    float* out = (float*)d_out;               // [B, 128] float32

    int B = in_sizes[0] / NB;                 // 4096
    gfusedmax_kernel<<<B, THREADS>>>(x, A, out);
}

// round 3
// speedup vs baseline: 1.0986x; 1.0986x over previous
#include <cuda_runtime.h>

#define NB 128
#define THREADS 1024
#define NITER 60

typedef unsigned long long ull;

__device__ __forceinline__ ull pk2(float lo, float hi) {
    ull r; asm("mov.b64 %0, {%1, %2};" : "=l"(r) : "f"(lo), "f"(hi)); return r;
}
__device__ __forceinline__ void upk2(ull v, float& lo, float& hi) {
    asm("mov.b64 {%0, %1}, %2;" : "=f"(lo), "=f"(hi) : "l"(v));
}
__device__ __forceinline__ ull padd2(ull a, ull b) {
    ull r; asm("add.rn.f32x2 %0, %1, %2;" : "=l"(r) : "l"(a), "l"(b)); return r;
}
__device__ __forceinline__ ull psub2(ull a, ull b) {
    ull r; asm("sub.rn.f32x2 %0, %1, %2;" : "=l"(r) : "l"(a), "l"(b)); return r;
}

// Funnel-reduce 4 values over the full warp. Returns, on lane L, the full
// 32-lane sum of value j where j = ((L>>4)&1) | (((L>>3)&1)<<1).
__device__ __forceinline__ float merge_reduce4(float a0, float a1, float a2, float a3, int lane) {
    a0 += __shfl_xor_sync(0xffffffffu, a0, 16);
    a1 += __shfl_xor_sync(0xffffffffu, a1, 16);
    a2 += __shfl_xor_sync(0xffffffffu, a2, 16);
    a3 += __shfl_xor_sync(0xffffffffu, a3, 16);
    float b0 = (lane & 16) ? a1 : a0;
    float b1 = (lane & 16) ? a3 : a2;
    b0 += __shfl_xor_sync(0xffffffffu, b0, 8);
    b1 += __shfl_xor_sync(0xffffffffu, b1, 8);
    float c = (lane & 8) ? b1 : b0;
    c += __shfl_xor_sync(0xffffffffu, c, 4);
    c += __shfl_xor_sync(0xffffffffu, c, 2);
    c += __shfl_xor_sync(0xffffffffu, c, 1);
    return c;
}

__global__ void __launch_bounds__(THREADS, 1)
gfusedmax_kernel(const float* __restrict__ x,
                 const float* __restrict__ A,
                 float* __restrict__ out)
{
    const int b     = blockIdx.x;
    const int tid   = threadIdx.x;
    const int lane  = tid & 31;
    const int warp  = tid >> 5;
    const int rbase = warp * 4;          // warp w owns rows AND columns 4w..4w+3

    __shared__ float colpart[32][129];            // padded: writes & transposed reads conflict-free
    __shared__ __align__(16) float sy_row[NB];    // step * y
    __shared__ float ys_s[NB];
    __shared__ float sorted_s[NB];
    __shared__ float csum[2][NB];
    __shared__ float wsum[4], wcnt[4];

    const float step = 1.0f / 256.0f;

    // index j this lane's funnel result corresponds to, and the column it owns
    const int jidx = ((lane >> 4) & 1) | (((lane >> 3) & 1) << 1);
    const int mycol = rbase + jidx;

    // ---- load clip bounds into registers, z = 0 ----
    float wxr[4][2], wyr[4][2];
    ull z2[4][2];
    const float* Ab = A + (size_t)b * NB * NB;
    #pragma unroll
    for (int r = 0; r < 4; ++r) {
        #pragma unroll
        for (int cp = 0; cp < 2; ++cp) {
            wxr[r][cp] = Ab[(rbase + r) * NB + lane + 64 * cp];       // col lane+64cp
            wyr[r][cp] = Ab[(rbase + r) * NB + lane + 64 * cp + 32];  // col lane+64cp+32
            z2[r][cp]  = 0ULL;
        }
    }

    // per-lane x for the column this lane finalizes
    const float xu = x[(size_t)b * NB + mycol];

    // init sy = step * x  (warp w writes its own 4 columns; lanes 0,8,16,24)
    if ((lane & 7) == 0) sy_row[mycol] = step * xu;
    __syncthreads();

    // ---- 60 projected-gradient iterations ----
    #pragma unroll 1
    for (int it = 0; it < NITER; ++it) {
        float syc0 = sy_row[lane];
        float syc1 = sy_row[lane + 32];
        float syc2 = sy_row[lane + 64];
        float syc3 = sy_row[lane + 96];
        float4 s4  = *reinterpret_cast<const float4*>(&sy_row[rbase]); // broadcast
        ull c2_0 = pk2(syc0, syc1);
        ull c2_1 = pk2(syc2, syc3);
        float syr[4] = {s4.x, s4.y, s4.z, s4.w};

        ull colacc0 = 0ULL, colacc1 = 0ULL;
        ull rowacc2[4];

        #pragma unroll
        for (int r = 0; r < 4; ++r) {
            ull s2 = pk2(syr[r], syr[r]);
            // cp = 0 : cols (lane, lane+32)
            {
                ull v2 = padd2(z2[r][0], psub2(s2, c2_0));
                float vx, vy; upk2(v2, vx, vy);
                float wa = wxr[r][0], wb = wyr[r][0];
                vx = fminf(fmaxf(vx, -wa), wa);
                vy = fminf(fmaxf(vy, -wb), wb);
                ull zz = pk2(vx, vy);
                z2[r][0] = zz;
                colacc0 = padd2(colacc0, zz);
                rowacc2[r] = zz;
            }
            // cp = 1 : cols (lane+64, lane+96)
            {
                ull v2 = padd2(z2[r][1], psub2(s2, c2_1));
                float vx, vy; upk2(v2, vx, vy);
                float wa = wxr[r][1], wb = wyr[r][1];
                vx = fminf(fmaxf(vx, -wa), wa);
                vy = fminf(fmaxf(vy, -wb), wb);
                ull zz = pk2(vx, vy);
                z2[r][1] = zz;
                colacc1 = padd2(colacc1, zz);
                rowacc2[r] = padd2(rowacc2[r], zz);
            }
        }

        // column partials for all 4 owned columns (conflict-free: bank = (lane + K) % 32)
        {
            float ax, ay;
            upk2(colacc0, ax, ay);
            colpart[warp][lane]      = ax;
            colpart[warp][lane + 32] = ay;
            upk2(colacc1, ax, ay);
            colpart[warp][lane + 64] = ax;
            colpart[warp][lane + 96] = ay;
        }

        // row sums (in-warp): funnel reduce; lane ends with rs[4w + jidx]
        float ra0, ra1, ra2, ra3;
        { float lo, hi;
          upk2(rowacc2[0], lo, hi); ra0 = lo + hi;
          upk2(rowacc2[1], lo, hi); ra1 = lo + hi;
          upk2(rowacc2[2], lo, hi); ra2 = lo + hi;
          upk2(rowacc2[3], lo, hi); ra3 = lo + hi; }
        float rsum = merge_reduce4(ra0, ra1, ra2, ra3, lane);

        __syncthreads();

        // column sums for owned columns: transposed read (conflict-free via pad)
        float p0 = colpart[lane][rbase + 0];
        float p1 = colpart[lane][rbase + 1];
        float p2 = colpart[lane][rbase + 2];
        float p3 = colpart[lane][rbase + 3];
        float csumv = merge_reduce4(p0, p1, p2, p3, lane);

        // y for column (4w + jidx), same lane holds rsum and csumv for it
        float y = xu - rsum + csumv;
        if ((lane & 7) == 0) sy_row[mycol] = step * y;

        __syncthreads();
    }

    // ---- final y (exact: /256 then *256 is exponent-only) ----
    float yv = 0.0f;
    if (tid < NB) {
        yv = sy_row[tid] * 256.0f;
        ys_s[tid] = yv;
    }
    __syncthreads();

    // ---- sparsemax: rank sort (branch-free, deterministic) ----
    if (tid < NB) {
        int rank = 0;
        #pragma unroll
        for (int j = 0; j < NB; ++j) {
            float uj = ys_s[j];
            rank += (uj > yv) || (uj == yv && j < tid);
        }
        sorted_s[rank] = yv;                   // descending
    }
    __syncthreads();

    // inclusive scan (Hillis-Steele, ping-pong)
    if (tid < NB) csum[0][tid] = sorted_s[tid];
    __syncthreads();
    int src = 0;
    for (int off = 1; off < NB; off <<= 1) {
        if (tid < NB) {
            float vv = csum[src][tid];
            if (tid >= off) vv += csum[src][tid - off];
            csum[1 - src][tid] = vv;
        }
        __syncthreads();
        src = 1 - src;
    }

    // mask + deterministic (sum, count) reduction
    if (tid < NB) {
        float s  = sorted_s[tid];
        float cu = csum[src][tid];
        float k  = (float)(tid + 1);
        bool  m  = (1.0f + k * s > cu);
        float sv = m ? s : 0.0f;
        float sc = m ? 1.0f : 0.0f;
        #pragma unroll
        for (int sft = 16; sft > 0; sft >>= 1) {
            sv += __shfl_xor_sync(0xffffffffu, sv, sft);
            sc += __shfl_xor_sync(0xffffffffu, sc, sft);
        }
        if (lane == 0) { wsum[warp] = sv; wcnt[warp] = sc; }
    }
    __syncthreads();

    if (tid < NB) {
        float ssum = ((wsum[0] + wsum[1]) + (wsum[2] + wsum[3]));
        float scnt = ((wcnt[0] + wcnt[1]) + (wcnt[2] + wcnt[3]));
        float tau  = (ssum - 1.0f) / scnt;
        out[(size_t)b * NB + tid] = fmaxf(yv - tau, 0.0f);
    }
}

extern "C" void kernel_launch(void* const* d_in, const int* in_sizes, int n_in,
                              void* d_out, int out_size)
{
    const float* x = (const float*)d_in[0];   // [B, 128]
    const float* A = (const float*)d_in[1];   // [B, 128, 128]
    float* out = (float*)d_out;               // [B, 128] float32

    int B = in_sizes[0] / NB;                 // 4096
    gfusedmax_kernel<<<B, THREADS>>>(x, A, out);
}